// round 4
// baseline (speedup 1.0000x reference)
#include <cuda_runtime.h>

#define NB 8
#define NI 64
#define NO 64
#define NN 8192
#define NK 16
#define ND 3
#define NH1 16
#define NH2 32
#define TN 8                 // n values per CTA
#define ROWS 128             // TN * NK
#define NTHREADS 256
#define BON (NB*NO*NN)       // 4194304
#define SPN (NB*ND*NN)       // 196608

typedef unsigned long long u64;

// shared memory layout (floats):
//  sWd  : 2*NI*NO  = 8192   (duplicated weight, u64 lanes)
//  sX   : NI*ROWS  = 8192
//  sH2  : NH2*ROWS = 4096
//  sW3d : 2*NH2*NO = 4096   (duplicated W3)
//  small: 48+16+512+32+64+64+512 = 1248
#define SMEM_FLOATS (8192+8192+4096+4096+1248)
#define SMEM_BYTES (SMEM_FLOATS*4)

__device__ __forceinline__ u64 pack2(float x, float y) {
    u64 r; asm("mov.b64 %0,{%1,%2};" : "=l"(r) : "f"(x), "f"(y)); return r;
}
__device__ __forceinline__ u64 fma2(u64 a, u64 b, u64 c) {
    u64 d; asm("fma.rn.f32x2 %0,%1,%2,%3;" : "=l"(d) : "l"(a), "l"(b), "l"(c)); return d;
}
__device__ __forceinline__ float2 unpack2(u64 v) {
    float2 f; asm("mov.b64 {%0,%1},%2;" : "=f"(f.x), "=f"(f.y) : "l"(v)); return f;
}

__global__ void __launch_bounds__(NTHREADS, 2)
pccn_kernel(const float* __restrict__ input, const float* __restrict__ points,
            const float* __restrict__ support, const float* __restrict__ weight,
            const float* __restrict__ bias, const float* __restrict__ W1,
            const float* __restrict__ b1, const float* __restrict__ W2,
            const float* __restrict__ b2, const float* __restrict__ W3,
            const float* __restrict__ b3, float* __restrict__ out, int copy_sp)
{
    extern __shared__ float sm[];
    u64*   sWd   = (u64*)sm;              // [i][o] duplicated, 4096 u64
    float* sX    = sm  + 8192;            // [i][row]
    float* sH2   = sX  + 8192;            // [j][row]
    u64*   sW3d  = (u64*)(sH2 + 4096);    // [j][o] duplicated, 2048 u64
    float* sW1   = (float*)(sW3d + 2048); // 3x16
    float* sb1   = sW1 + 48;
    float* sW2   = sb1 + 16;              // 16x32
    float* sb2   = sW2 + 512;
    float* sb3   = sb2 + 32;
    float* sBias = sb3 + 64;
    float* sOut  = sBias + 64;            // [n_local][o] 8x64

    const int tid = threadIdx.x;
    const int blk = blockIdx.x;
    const int b   = blk >> 10;            // NN/TN = 1024 tiles per batch
    const int n0  = (blk & 1023) * TN;

    // ---- cooperative loads to smem ----
    // duplicated weight: each float -> (w,w) u64
    for (int idx = tid; idx < NI*NO; idx += NTHREADS) {
        float w = weight[idx];
        sWd[idx] = pack2(w, w);
    }
    for (int idx = tid; idx < NH2*NO; idx += NTHREADS) {
        float w = W3[idx];
        sW3d[idx] = pack2(w, w);
    }
    for (int idx = tid; idx < (NI*ROWS)/4; idx += NTHREADS) {
        int i = idx >> 5, c = idx & 31;   // 32 float4 per i-row
        ((float4*)(sX + i*ROWS))[c] =
            *(const float4*)(input + (((size_t)b*NI + i)*NN + n0)*NK + c*4);
    }
    for (int idx = tid; idx < NH1*NH2; idx += NTHREADS) sW2[idx] = W2[idx];
    if (tid < 48) sW1[tid]  = W1[tid];
    if (tid < 16) sb1[tid]  = b1[tid];
    if (tid < 32) sb2[tid]  = b2[tid];
    if (tid < 64) sb3[tid]  = b3[tid];
    if (tid < 64) sBias[tid] = bias[tid];

    // ---- per-row (b,n,k) relative coords + normalization (threads 0..127) ----
    float x0 = 0.f, x1 = 0.f, x2 = 0.f;
    if (tid < ROWS) {
        const int k = tid & 15;
        const int n = n0 + (tid >> 4);
        float p0 = points[(((size_t)b*ND + 0)*NN + n)*NK + k] - support[((size_t)b*ND + 0)*NN + n];
        float p1 = points[(((size_t)b*ND + 1)*NN + n)*NK + k] - support[((size_t)b*ND + 1)*NN + n];
        float p2 = points[(((size_t)b*ND + 2)*NN + n)*NK + k] - support[((size_t)b*ND + 2)*NN + n];
        float sq = p0*p0 + p1*p1 + p2*p2;
        float m = sq;
#pragma unroll
        for (int off = 8; off > 0; off >>= 1)
            m = fmaxf(m, __shfl_xor_sync(0xffffffffu, m, off));
        float maxi = sqrtf(m);
        maxi += (maxi == 0.0f) ? 1.0f : 0.0f;
        float inv = 1.0f / maxi;
        x0 = p0*inv; x1 = p1*inv; x2 = p2*inv;
    }

    __syncthreads();   // weights ready

    // ---- tiny MLP to h2 (threads 0..127, one row each) ----
    if (tid < ROWS) {
        float h1[NH1];
#pragma unroll
        for (int a = 0; a < NH1; a++) {
            float v = sb1[a] + x0*sW1[a] + x1*sW1[16 + a] + x2*sW1[32 + a];
            h1[a] = fmaxf(v, 0.0f);
        }
        u64 h2p[NH2/2];
#pragma unroll
        for (int jp = 0; jp < NH2/2; jp++) h2p[jp] = ((const u64*)sb2)[jp];
#pragma unroll
        for (int a = 0; a < NH1; a++) {
            u64 xd = pack2(h1[a], h1[a]);
            const u64* wrow = (const u64*)(sW2 + a*NH2);
#pragma unroll
            for (int jp = 0; jp < NH2/2; jp++) h2p[jp] = fma2(xd, wrow[jp], h2p[jp]);
        }
#pragma unroll
        for (int jp = 0; jp < NH2/2; jp++) {
            float2 v = unpack2(h2p[jp]);
            sH2[(2*jp+0)*ROWS + tid] = fmaxf(v.x, 0.0f);
            sH2[(2*jp+1)*ROWS + tid] = fmaxf(v.y, 0.0f);
        }
    }

    __syncthreads();

    // ---- two register-tiled GEMMs, per-thread tile 4 rows x 8 o ----
    // f32x2 lanes packed along rows: acc (row r, row r+1)
    const int tr = tid >> 3, tc = tid & 7;
    const int row0 = tr * 4, o0 = tc * 8;

    // mat = h2 @ W3 + b3   (K-dim 32)
    u64 macc[2][8];
    {
#pragma unroll
        for (int oo = 0; oo < 8; oo++) {
            float bv = sb3[o0 + oo];
            u64 bp = pack2(bv, bv);
            macc[0][oo] = bp; macc[1][oo] = bp;
        }
    }
#pragma unroll 4
    for (int j = 0; j < NH2; j++) {
        ulonglong2 xv = *(const ulonglong2*)(sH2 + j*ROWS + row0);
        const ulonglong2* wp = (const ulonglong2*)(sW3d + j*NO + o0);
        ulonglong2 wa = wp[0], wb = wp[1], wc = wp[2], wd = wp[3];
        u64 w[8] = {wa.x, wa.y, wb.x, wb.y, wc.x, wc.y, wd.x, wd.y};
#pragma unroll
        for (int oo = 0; oo < 8; oo++) {
            macc[0][oo] = fma2(xv.x, w[oo], macc[0][oo]);
            macc[1][oo] = fma2(xv.y, w[oo], macc[1][oo]);
        }
    }

    // F = X^T @ weight   (K-dim 64)
    u64 facc[2][8];
#pragma unroll
    for (int oo = 0; oo < 8; oo++) { facc[0][oo] = 0ull; facc[1][oo] = 0ull; }

#pragma unroll 4
    for (int i = 0; i < NI; i++) {
        ulonglong2 xv = *(const ulonglong2*)(sX + i*ROWS + row0);
        const ulonglong2* wp = (const ulonglong2*)(sWd + i*NO + o0);
        ulonglong2 wa = wp[0], wb = wp[1], wc = wp[2], wd = wp[3];
        u64 w[8] = {wa.x, wa.y, wb.x, wb.y, wc.x, wc.y, wd.x, wd.y};
#pragma unroll
        for (int oo = 0; oo < 8; oo++) {
            facc[0][oo] = fma2(xv.x, w[oo], facc[0][oo]);
            facc[1][oo] = fma2(xv.y, w[oo], facc[1][oo]);
        }
    }

    // ---- combine: elementwise product, reduce over 4 rows in-thread ----
    float v[8];
#pragma unroll
    for (int oo = 0; oo < 8; oo++) {
        u64 p = fma2(facc[0][oo], macc[0][oo], 0ull);
        p = fma2(facc[1][oo], macc[1][oo], p);
        float2 f = unpack2(p);
        v[oo] = f.x + f.y;
    }
    // reduce across the 4 lanes (xor 8, 16) that share (n_local, o0)
#pragma unroll
    for (int oo = 0; oo < 8; oo++) {
        v[oo] += __shfl_xor_sync(0xffffffffu, v[oo], 8);
        v[oo] += __shfl_xor_sync(0xffffffffu, v[oo], 16);
    }
    // warp w owns n_local = w; lanes 0..7 write 8 o each
    const int lid = tid & 31;
    const int n_local = tid >> 5;
    if (lid < 8) {
        float4 a = make_float4(v[0], v[1], v[2], v[3]);
        float4 c = make_float4(v[4], v[5], v[6], v[7]);
        *(float4*)(sOut + n_local*NO + o0)     = a;
        *(float4*)(sOut + n_local*NO + o0 + 4) = c;
    }

    __syncthreads();

    // ---- epilogue: out layout (B, O, N), + bias ----
    if (tid < 128) {
        int o = tid >> 1, half = tid & 1;
        float4 r;
        r.x = sOut[(half*4+0)*NO + o] + sBias[o];
        r.y = sOut[(half*4+1)*NO + o] + sBias[o];
        r.z = sOut[(half*4+2)*NO + o] + sBias[o];
        r.w = sOut[(half*4+3)*NO + o] + sBias[o];
        *(float4*)(out + ((size_t)b*NO + o)*NN + n0 + half*4) = r;
    }

    // ---- second tuple element: support_points passthrough ----
    if (copy_sp) {
        for (int idx = blk*NTHREADS + tid; idx < SPN; idx += gridDim.x*NTHREADS)
            out[BON + idx] = support[idx];
    }
}

extern "C" void kernel_launch(void* const* d_in, const int* in_sizes, int n_in,
                              void* d_out, int out_size) {
    const float* input   = (const float*)d_in[0];
    const float* points  = (const float*)d_in[1];
    const float* support = (const float*)d_in[2];
    const float* weight  = (const float*)d_in[3];
    const float* bias    = (const float*)d_in[4];
    const float* W1      = (const float*)d_in[5];
    const float* b1      = (const float*)d_in[6];
    const float* W2      = (const float*)d_in[7];
    const float* b2      = (const float*)d_in[8];
    const float* W3      = (const float*)d_in[9];
    const float* b3      = (const float*)d_in[10];

    static int inited = 0;
    if (!inited) {
        cudaFuncSetAttribute(pccn_kernel,
                             cudaFuncAttributeMaxDynamicSharedMemorySize,
                             SMEM_BYTES);
        inited = 1;
    }
    int copy_sp = (out_size > BON) ? 1 : 0;
    pccn_kernel<<<NB*(NN/TN), NTHREADS, SMEM_BYTES>>>(
        input, points, support, weight, bias, W1, b1, W2, b2, W3, b3,
        (float*)d_out, copy_sp);
}

// round 5
// speedup vs baseline: 3.5821x; 3.5821x over previous
#include <cuda_runtime.h>

#define NB 8
#define NI 64
#define NO 64
#define NN 8192
#define NK 16
#define ND 3
#define NH1 16
#define NH2 32
#define TN 8                 // n values per CTA
#define ROWS 128             // TN * NK
#define NTHREADS 256
#define BON (NB*NO*NN)       // 4194304
#define SPN (NB*ND*NN)       // 196608

typedef unsigned long long u64;

// shared memory layout (floats):
//  sWp  : NI*NO   = 4096   (permuted weight)
//  sX   : NI*ROWS = 8192
//  sH2  : NH2*ROWS= 4096
//  sW3p : NH2*NO  = 2048   (permuted W3)
//  small: 48+16+512+32+64+64+512 = 1248
#define SMEM_FLOATS (4096+8192+4096+2048+1248)
#define SMEM_BYTES (SMEM_FLOATS*4)

__device__ __forceinline__ u64 pack2(float x, float y) {
    u64 r; asm("mov.b64 %0,{%1,%2};" : "=l"(r) : "f"(x), "f"(y)); return r;
}
__device__ __forceinline__ u64 fma2(u64 a, u64 b, u64 c) {
    u64 d; asm("fma.rn.f32x2 %0,%1,%2,%3;" : "=l"(d) : "l"(a), "l"(b), "l"(c)); return d;
}
__device__ __forceinline__ float2 unpack2(u64 v) {
    float2 f; asm("mov.b64 {%0,%1},%2;" : "=f"(f.x), "=f"(f.y) : "l"(v)); return f;
}

// permuted index within a 64-float weight row: all tc half0 chunks, then half1.
// o -> ((o>>2)&1)*32 + (o>>3)*4 + (o&3)
__device__ __forceinline__ int wperm(int o) {
    return ((o >> 2) & 1) * 32 + (o >> 3) * 4 + (o & 3);
}

__global__ void __launch_bounds__(NTHREADS, 2)
pccn_kernel(const float* __restrict__ input, const float* __restrict__ points,
            const float* __restrict__ support, const float* __restrict__ weight,
            const float* __restrict__ bias, const float* __restrict__ W1,
            const float* __restrict__ b1, const float* __restrict__ W2,
            const float* __restrict__ b2, const float* __restrict__ W3,
            const float* __restrict__ b3, float* __restrict__ out, int copy_sp)
{
    extern __shared__ float sm[];
    float* sWp   = sm;                    // [i][perm(o)]
    float* sX    = sWp + 4096;            // [i][row]
    float* sH2   = sX  + 8192;            // [j][row]
    float* sW3p  = sH2 + 4096;            // [j][perm(o)]
    float* sW1   = sW3p + 2048;           // 3x16
    float* sb1   = sW1 + 48;
    float* sW2   = sb1 + 16;              // 16x32
    float* sb2   = sW2 + 512;
    float* sb3   = sb2 + 32;
    float* sBias = sb3 + 64;
    float* sOut  = sBias + 64;            // [n_local][o] 8x64

    const int tid = threadIdx.x;
    const int blk = blockIdx.x;
    const int b   = blk >> 10;            // NN/TN = 1024 tiles per batch
    const int n0  = (blk & 1023) * TN;

    // ---- cooperative loads to smem ----
    for (int idx = tid; idx < NI*NO; idx += NTHREADS) {
        int i = idx >> 6, o = idx & 63;
        sWp[i*NO + wperm(o)] = weight[idx];
    }
    for (int idx = tid; idx < NH2*NO; idx += NTHREADS) {
        int j = idx >> 6, o = idx & 63;
        sW3p[j*NO + wperm(o)] = W3[idx];
    }
    for (int idx = tid; idx < (NI*ROWS)/4; idx += NTHREADS) {
        int i = idx >> 5, c = idx & 31;   // 32 float4 per i-row
        ((float4*)(sX + i*ROWS))[c] =
            *(const float4*)(input + (((size_t)b*NI + i)*NN + n0)*NK + c*4);
    }
    for (int idx = tid; idx < NH1*NH2; idx += NTHREADS) sW2[idx] = W2[idx];
    if (tid < 48) sW1[tid]  = W1[tid];
    if (tid < 16) sb1[tid]  = b1[tid];
    if (tid < 32) sb2[tid]  = b2[tid];
    if (tid < 64) sb3[tid]  = b3[tid];
    if (tid < 64) sBias[tid] = bias[tid];

    // ---- per-row (b,n,k) relative coords + normalization (threads 0..127) ----
    float x0 = 0.f, x1 = 0.f, x2 = 0.f;
    if (tid < ROWS) {
        const int k = tid & 15;
        const int n = n0 + (tid >> 4);
        float p0 = points[(((size_t)b*ND + 0)*NN + n)*NK + k] - support[((size_t)b*ND + 0)*NN + n];
        float p1 = points[(((size_t)b*ND + 1)*NN + n)*NK + k] - support[((size_t)b*ND + 1)*NN + n];
        float p2 = points[(((size_t)b*ND + 2)*NN + n)*NK + k] - support[((size_t)b*ND + 2)*NN + n];
        float sq = p0*p0 + p1*p1 + p2*p2;
        float m = sq;
#pragma unroll
        for (int off = 8; off > 0; off >>= 1)
            m = fmaxf(m, __shfl_xor_sync(0xffffffffu, m, off));
        float maxi = sqrtf(m);
        maxi += (maxi == 0.0f) ? 1.0f : 0.0f;
        float inv = 1.0f / maxi;
        x0 = p0*inv; x1 = p1*inv; x2 = p2*inv;
    }

    __syncthreads();   // weights ready

    // ---- tiny MLP to h2 (threads 0..127, one row each) ----
    if (tid < ROWS) {
        float h1[NH1];
#pragma unroll
        for (int a = 0; a < NH1; a++) {
            float v = sb1[a] + x0*sW1[a] + x1*sW1[16 + a] + x2*sW1[32 + a];
            h1[a] = fmaxf(v, 0.0f);
        }
        u64 h2p[NH2/2];
#pragma unroll
        for (int jp = 0; jp < NH2/2; jp++) h2p[jp] = ((const u64*)sb2)[jp];
#pragma unroll
        for (int a = 0; a < NH1; a++) {
            u64 xd = pack2(h1[a], h1[a]);
            const u64* wrow = (const u64*)(sW2 + a*NH2);
#pragma unroll
            for (int jp = 0; jp < NH2/2; jp++) h2p[jp] = fma2(xd, wrow[jp], h2p[jp]);
        }
#pragma unroll
        for (int jp = 0; jp < NH2/2; jp++) {
            float2 v = unpack2(h2p[jp]);
            sH2[(2*jp+0)*ROWS + tid] = fmaxf(v.x, 0.0f);
            sH2[(2*jp+1)*ROWS + tid] = fmaxf(v.y, 0.0f);
        }
    }

    __syncthreads();

    // ---- two register-tiled GEMMs, per-thread tile 4 rows x 8 o ----
    // f32x2 acc packed along o: macc[rr][op] = (o0+2op, o0+2op+1)
    const int tr = tid >> 3, tc = tid & 7;
    const int row0 = tr * 4, o0 = tc * 8;
    const int wofs = tc * 4;                 // float offset of this thread's half0 chunk

    // mat = h2 @ W3 + b3   (K-dim 32)
    u64 macc[4][4];
    {
#pragma unroll
        for (int op = 0; op < 4; op++) {
            u64 bp = pack2(sb3[o0 + 2*op], sb3[o0 + 2*op + 1]);
            macc[0][op] = bp; macc[1][op] = bp; macc[2][op] = bp; macc[3][op] = bp;
        }
    }
#pragma unroll 4
    for (int j = 0; j < NH2; j++) {
        const float4 xa = *(const float4*)(sH2 + j*ROWS + row0);
        u64 xd[4];
        xd[0]=pack2(xa.x,xa.x); xd[1]=pack2(xa.y,xa.y);
        xd[2]=pack2(xa.z,xa.z); xd[3]=pack2(xa.w,xa.w);
        const ulonglong2* wp = (const ulonglong2*)(sW3p + j*NO + wofs);
        ulonglong2 wlo = wp[0];    // o0..o0+3
        ulonglong2 whi = wp[8];    // o0+4..o0+7  (+32 floats)
        u64 w[4] = {wlo.x, wlo.y, whi.x, whi.y};
#pragma unroll
        for (int rr = 0; rr < 4; rr++)
#pragma unroll
            for (int op = 0; op < 4; op++)
                macc[rr][op] = fma2(xd[rr], w[op], macc[rr][op]);
    }

    // F = X^T @ weight   (K-dim 64)
    u64 facc[4][4];
#pragma unroll
    for (int rr = 0; rr < 4; rr++)
#pragma unroll
        for (int op = 0; op < 4; op++) facc[rr][op] = 0ull;

#pragma unroll 4
    for (int i = 0; i < NI; i++) {
        const float4 xa = *(const float4*)(sX + i*ROWS + row0);
        u64 xd[4];
        xd[0]=pack2(xa.x,xa.x); xd[1]=pack2(xa.y,xa.y);
        xd[2]=pack2(xa.z,xa.z); xd[3]=pack2(xa.w,xa.w);
        const ulonglong2* wp = (const ulonglong2*)(sWp + i*NO + wofs);
        ulonglong2 wlo = wp[0];
        ulonglong2 whi = wp[8];
        u64 w[4] = {wlo.x, wlo.y, whi.x, whi.y};
#pragma unroll
        for (int rr = 0; rr < 4; rr++)
#pragma unroll
            for (int op = 0; op < 4; op++)
                facc[rr][op] = fma2(xd[rr], w[op], facc[rr][op]);
    }

    // ---- combine: elementwise product, reduce over 4 rows in-thread ----
    float v[8];
#pragma unroll
    for (int op = 0; op < 4; op++) {
        u64 p = fma2(facc[0][op], macc[0][op], 0ull);
        p = fma2(facc[1][op], macc[1][op], p);
        p = fma2(facc[2][op], macc[2][op], p);
        p = fma2(facc[3][op], macc[3][op], p);
        float2 f = unpack2(p);
        v[2*op]   = f.x;
        v[2*op+1] = f.y;
    }
    // reduce across the 4 lanes (xor 8, 16) that share (n_local, o0)
#pragma unroll
    for (int oo = 0; oo < 8; oo++) {
        v[oo] += __shfl_xor_sync(0xffffffffu, v[oo], 8);
        v[oo] += __shfl_xor_sync(0xffffffffu, v[oo], 16);
    }
    // warp w owns n_local = w; lanes 0..7 write 8 o each
    const int lid = tid & 31;
    const int n_local = tid >> 5;
    if (lid < 8) {
        float4 a = make_float4(v[0], v[1], v[2], v[3]);
        float4 c = make_float4(v[4], v[5], v[6], v[7]);
        *(float4*)(sOut + n_local*NO + lid*8)     = a;
        *(float4*)(sOut + n_local*NO + lid*8 + 4) = c;
    }

    __syncthreads();

    // ---- epilogue: out layout (B, O, N), + bias ----
    if (tid < 128) {
        int o = tid >> 1, half = tid & 1;
        float4 r;
        r.x = sOut[(half*4+0)*NO + o] + sBias[o];
        r.y = sOut[(half*4+1)*NO + o] + sBias[o];
        r.z = sOut[(half*4+2)*NO + o] + sBias[o];
        r.w = sOut[(half*4+3)*NO + o] + sBias[o];
        *(float4*)(out + ((size_t)b*NO + o)*NN + n0 + half*4) = r;
    }

    // ---- second tuple element: support_points passthrough ----
    if (copy_sp) {
        for (int idx = blk*NTHREADS + tid; idx < SPN; idx += gridDim.x*NTHREADS)
            out[BON + idx] = support[idx];
    }
}

extern "C" void kernel_launch(void* const* d_in, const int* in_sizes, int n_in,
                              void* d_out, int out_size) {
    const float* input   = (const float*)d_in[0];
    const float* points  = (const float*)d_in[1];
    const float* support = (const float*)d_in[2];
    const float* weight  = (const float*)d_in[3];
    const float* bias    = (const float*)d_in[4];
    const float* W1      = (const float*)d_in[5];
    const float* b1      = (const float*)d_in[6];
    const float* W2      = (const float*)d_in[7];
    const float* b2      = (const float*)d_in[8];
    const float* W3      = (const float*)d_in[9];
    const float* b3      = (const float*)d_in[10];

    static int inited = 0;
    if (!inited) {
        cudaFuncSetAttribute(pccn_kernel,
                             cudaFuncAttributeMaxDynamicSharedMemorySize,
                             SMEM_BYTES);
        inited = 1;
    }
    int copy_sp = (out_size > BON) ? 1 : 0;
    pccn_kernel<<<NB*(NN/TN), NTHREADS, SMEM_BYTES>>>(
        input, points, support, weight, bias, W1, b1, W2, b2, W3, b3,
        (float*)d_out, copy_sp);
}